// round 2
// baseline (speedup 1.0000x reference)
#include <cuda_runtime.h>

#define BB 32
#define KK 10
#define NN 128
#define FF 512
#define NITER 30
#define LRc 0.5f
#define RHOc 10.0f

// ---- scratch (static device globals: allocation-free) ----
static __device__ float g_C[BB * NN * NN];                 // 2 MB
static __device__ float g_S[(size_t)BB * KK * NN * NN];    // 21 MB softmax probs
static __device__ float g_P[BB * KK * NN];
static __device__ float g_cost[BB * KK];
static __device__ float g_w[BB * KK * NN];
static __device__ float g_a[BB * KK];
static __device__ float g_xn[BB * NN];
static __device__ float g_Crow[BB * NN];                   // row sums of C
static __device__ int   g_ticket[BB];

__device__ __forceinline__ float wsum(float v) {
#pragma unroll
    for (int o = 16; o; o >>= 1) v += __shfl_xor_sync(0xffffffffu, v, o);
    return v;
}
__device__ __forceinline__ float hsum16(float v) {
#pragma unroll
    for (int o = 8; o; o >>= 1) v += __shfl_xor_sync(0xffffffffu, v, o);
    return v;
}
__device__ __forceinline__ float hmax16(float v) {
#pragma unroll
    for (int o = 8; o; o >>= 1) v = fmaxf(v, __shfl_xor_sync(0xffffffffu, v, o));
    return v;
}

// ---- xn[b][i] = sum_f X^2 ----
__global__ void xn_kernel(const float* __restrict__ X) {
    int b = blockIdx.x;
    int w = threadIdx.x >> 5, lane = threadIdx.x & 31;
    for (int l = w; l < NN; l += 8) {
        const float4* xr = (const float4*)(X + ((size_t)b * NN + l) * FF);
        float acc = 0.f;
#pragma unroll
        for (int q = 0; q < FF / 128; q++) {
            float4 v = xr[lane + 32 * q];
            acc += v.x * v.x + v.y * v.y + v.z * v.z + v.w * v.w;
        }
        acc = wsum(acc);
        if (lane == 0) g_xn[b * NN + l] = acc;
    }
}

// ---- G = X X^T per b, 64x64 tiles ----
__global__ void gemm_kernel(const float* __restrict__ X) {
    int b = blockIdx.z;
    int ti = blockIdx.y * 64, tj = blockIdx.x * 64;
    __shared__ float As[16][64];
    __shared__ float Bs[16][64];
    const float* Xb = X + (size_t)b * NN * FF;
    int t = threadIdx.x;
    int lr = t >> 2, lq = t & 3;
    int tx = t & 15, ty = t >> 4;
    float acc[4][4];
#pragma unroll
    for (int i = 0; i < 4; i++)
#pragma unroll
        for (int j = 0; j < 4; j++) acc[i][j] = 0.f;

    for (int kc = 0; kc < FF; kc += 16) {
        float4 av = *(const float4*)(Xb + (size_t)(ti + lr) * FF + kc + lq * 4);
        float4 bv = *(const float4*)(Xb + (size_t)(tj + lr) * FF + kc + lq * 4);
        if (kc) __syncthreads();
        As[lq * 4 + 0][lr] = av.x; As[lq * 4 + 1][lr] = av.y;
        As[lq * 4 + 2][lr] = av.z; As[lq * 4 + 3][lr] = av.w;
        Bs[lq * 4 + 0][lr] = bv.x; Bs[lq * 4 + 1][lr] = bv.y;
        Bs[lq * 4 + 2][lr] = bv.z; Bs[lq * 4 + 3][lr] = bv.w;
        __syncthreads();
#pragma unroll
        for (int kk = 0; kk < 16; kk++) {
            float4 af = *(const float4*)&As[kk][ty * 4];
            float4 bf = *(const float4*)&Bs[kk][tx * 4];
            float a[4] = {af.x, af.y, af.z, af.w};
            float bb4[4] = {bf.x, bf.y, bf.z, bf.w};
#pragma unroll
            for (int i = 0; i < 4; i++)
#pragma unroll
                for (int j = 0; j < 4; j++) acc[i][j] = fmaf(a[i], bb4[j], acc[i][j]);
        }
    }
#pragma unroll
    for (int i = 0; i < 4; i++) {
        float4 o; o.x = acc[i][0]; o.y = acc[i][1]; o.z = acc[i][2]; o.w = acc[i][3];
        *(float4*)(g_C + ((size_t)b * NN + ti + ty * 4 + i) * NN + tj + tx * 4) = o;
    }
}

// ---- C = clip(dist - diag_col, 0), in-place, + row sums ----
__global__ void finC_kernel() {
    int b = blockIdx.x;
    __shared__ float xns[NN], dgv[NN];
    float* Gb = g_C + (size_t)b * NN * NN;
    for (int j = threadIdx.x; j < NN; j += 256) {
        float xj = g_xn[b * NN + j];
        xns[j] = xj;
        dgv[j] = xj + xj - 2.0f * Gb[j * NN + j];
    }
    __syncthreads();
    int w = threadIdx.x >> 5, lane = threadIdx.x & 31;
    for (int i = w; i < NN; i += 8) {
        float xi = xns[i];
        float4 g = *(float4*)(Gb + i * NN + lane * 4);
        float c0 = fmaxf(xi + xns[lane * 4 + 0] - 2.0f * g.x - dgv[lane * 4 + 0], 0.f);
        float c1 = fmaxf(xi + xns[lane * 4 + 1] - 2.0f * g.y - dgv[lane * 4 + 1], 0.f);
        float c2 = fmaxf(xi + xns[lane * 4 + 2] - 2.0f * g.z - dgv[lane * 4 + 2], 0.f);
        float c3 = fmaxf(xi + xns[lane * 4 + 3] - 2.0f * g.w - dgv[lane * 4 + 3], 0.f);
        *(float4*)(Gb + i * NN + lane * 4) = make_float4(c0, c1, c2, c3);
        float rs = wsum(c0 + c1 + c2 + c3);
        if (lane == 0) g_Crow[b * NN + i] = rs;
    }
}

// ---- init: a0 from cost0 = sum_l q_l * rowmean_l(C). p0 uniform -> w const -> cancels ----
__global__ void init0_kernel(const float* __restrict__ Q, const float* __restrict__ theta) {
    int k = blockIdx.x, b = blockIdx.y;
    int tid = threadIdx.x;  // 128
    float v = Q[(b * KK + k) * NN + tid] * g_Crow[b * NN + tid] * (1.0f / NN);
    __shared__ float part[4];
    v = wsum(v);
    if ((tid & 31) == 0) part[tid >> 5] = v;
    __syncthreads();
    if (tid == 0) {
        float c = part[0] + part[1] + part[2] + part[3];
        float pen = c - theta[b * KK + k];
        g_a[b * KK + k] = (pen > 0.f) ? (2.f * RHOc * pen) : 0.f;
    }
}

// ---- per-b epilogue: min over k (JAX tie split), penalty coeff ----
__device__ __forceinline__ void epilogue_b(int b, const float* __restrict__ theta) {
    int tid = threadIdx.x;
    if (tid < NN) {
        float pv[KK];
        float mn = 3.402823466e38f;
#pragma unroll
        for (int k = 0; k < KK; k++) {
            pv[k] = __ldcg(&g_P[(b * KK + k) * NN + tid]);
            mn = fminf(mn, pv[k]);
        }
        float cnt = 0.f;
#pragma unroll
        for (int k = 0; k < KK; k++) cnt += (pv[k] == mn) ? 1.f : 0.f;
        float iv = 1.f / cnt;
#pragma unroll
        for (int k = 0; k < KK; k++)
            g_w[(b * KK + k) * NN + tid] = (pv[k] == mn) ? iv : 0.f;
    } else if (tid < NN + KK) {
        int k = tid - NN;
        float pen = __ldcg(&g_cost[b * KK + k]) - theta[b * KK + k];
        g_a[b * KK + k] = (pen > 0.f) ? (2.f * RHOc * pen) : 0.f;
    }
    if (tid == 0) g_ticket[b] = 0;
}

__device__ __forceinline__ void ticket_and_epilogue(int b, const float* __restrict__ theta,
                                                    int* flag_s) {
    __threadfence();
    __syncthreads();
    if (threadIdx.x == 0) {
        int old = atomicAdd(&g_ticket[b], 1);
        *flag_s = (old == KK - 1) ? 1 : 0;
    }
    __syncthreads();
    if (*flag_s) {
        __threadfence();
        epilogue_b(b, theta);
    }
}

// ---- one mirror-ascent iteration in probability space ----
__global__ void __launch_bounds__(512) iter_kernel(
        const float* __restrict__ Q, const float* __restrict__ theta,
        float* __restrict__ p_out, int first, int last) {
    int k = blockIdx.x, b = blockIdx.y;
    int tid = threadIdx.x;
    int warp = tid >> 5, lane = tid & 31;
    int h = lane >> 4, hl = lane & 15;
    __shared__ float w_s[NN];
    __shared__ float p_s[NN];
    __shared__ float cost_s;
    __shared__ int flag_s;

    float a = g_a[b * KK + k];
    for (int j = tid; j < NN; j += 512) {
        w_s[j] = first ? 0.f : g_w[(b * KK + k) * NN + j];
        p_s[j] = 0.f;
    }
    if (tid == 0) cost_s = 0.f;
    __syncthreads();

    float* Sbk = g_S + (size_t)(b * KK + k) * NN * NN;
    const float* Cb = g_C + (size_t)b * NN * NN;
    const float* Qr = Q + (b * KK + k) * NN;
    int j8 = hl * 8;

    float pacc[8];
#pragma unroll
    for (int i = 0; i < 8; i++) pacc[i] = 0.f;
    float cacc = 0.f;

#pragma unroll
    for (int pp = 0; pp < 4; pp++) {
        int l = pp * 32 + warp * 2 + h;
        float ql = Qr[l];
        float4 ca = *(const float4*)(Cb + l * NN + j8);
        float4 cb = *(const float4*)(Cb + l * NN + j8 + 4);
        float c[8] = {ca.x, ca.y, ca.z, ca.w, cb.x, cb.y, cb.z, cb.w};
        float s[8];
        if (first) {
#pragma unroll
            for (int i = 0; i < 8; i++) s[i] = 1.0f / 128.0f;
        } else {
            float4 sa = *(const float4*)(Sbk + l * NN + j8);
            float4 sb = *(const float4*)(Sbk + l * NN + j8 + 4);
            s[0] = sa.x; s[1] = sa.y; s[2] = sa.z; s[3] = sa.w;
            s[4] = sb.x; s[5] = sb.y; s[6] = sb.z; s[7] = sb.w;
        }
        float G[8], msum = 0.f;
#pragma unroll
        for (int i = 0; i < 8; i++) {
            G[i] = fmaf(-a, c[i], w_s[j8 + i]);
            msum = fmaf(s[i], G[i], msum);
        }
        msum = hsum16(msum);

        float lq = LRc * ql;
        float d[8], M = -3.0e38f;
#pragma unroll
        for (int i = 0; i < 8; i++) {
            d[i] = (s[i] > 0.f) ? lq * s[i] * (G[i] - msum) : -3.0e38f;
            M = fmaxf(M, d[i]);
        }
        M = hmax16(M);

        float e[8], r = 0.f;
#pragma unroll
        for (int i = 0; i < 8; i++) {
            e[i] = s[i] * __expf(d[i] - M);
            r += e[i];
        }
        r = hsum16(r);
        float ir = 1.0f / r;

        float t[8];
        float cdot = 0.f;
#pragma unroll
        for (int i = 0; i < 8; i++) {
            t[i] = e[i] * ir;
            pacc[i] = fmaf(ql, t[i], pacc[i]);
            cdot = fmaf(t[i], c[i], cdot);
        }
        cacc = fmaf(ql, cdot, cacc);

        if (!last) {
            *(float4*)(Sbk + l * NN + j8)     = make_float4(t[0], t[1], t[2], t[3]);
            *(float4*)(Sbk + l * NN + j8 + 4) = make_float4(t[4], t[5], t[6], t[7]);
        }
    }

#pragma unroll
    for (int i = 0; i < 8; i++) pacc[i] += __shfl_xor_sync(0xffffffffu, pacc[i], 16);
    if (h == 0) {
#pragma unroll
        for (int i = 0; i < 8; i++) atomicAdd(&p_s[j8 + i], pacc[i]);
    }
    cacc = wsum(cacc);
    if (lane == 0) atomicAdd(&cost_s, cacc);
    __syncthreads();

    if (last) {
        for (int j = tid; j < NN; j += 512)
            p_out[(b * KK + k) * NN + j] = p_s[j];
        return;
    }
    for (int j = tid; j < NN; j += 512)
        g_P[(b * KK + k) * NN + j] = p_s[j];
    if (tid == 0) g_cost[b * KK + k] = cost_s;

    ticket_and_epilogue(b, theta, &flag_s);
}

extern "C" void kernel_launch(void* const* d_in, const int* in_sizes, int n_in,
                              void* d_out, int out_size) {
    const float* X     = (const float*)d_in[0];  // [32,128,512]
    const float* Qp    = (const float*)d_in[1];  // [32,10,128]
    const float* theta = (const float*)d_in[2];  // [32,10]
    float* out = (float*)d_out;                  // [32,10,128]

    xn_kernel<<<BB, 256>>>(X);
    gemm_kernel<<<dim3(2, 2, BB), 256>>>(X);
    finC_kernel<<<BB, 256>>>();
    init0_kernel<<<dim3(KK, BB), 128>>>(Qp, theta);
    for (int t = 0; t < NITER; t++) {
        iter_kernel<<<dim3(KK, BB), 512>>>(Qp, theta, out,
                                           t == 0 ? 1 : 0,
                                           t == NITER - 1 ? 1 : 0);
    }
}

// round 3
// speedup vs baseline: 2.0844x; 2.0844x over previous
#include <cuda_runtime.h>

#define BB 32
#define KK 10
#define NN 128
#define FF 512
#define NITER 30
#define LRc 0.5f
#define RHOc 10.0f

// ---- scratch (static device globals: allocation-free) ----
static __device__ float g_C[BB * NN * NN];       // 2 MB cost matrix
static __device__ float g_P[2][BB * KK * NN];    // double-buffered column sums
static __device__ float g_a0[BB * KK];           // iter-0 penalty coeff
static __device__ float g_xn[BB * NN];
static __device__ float g_Crow[BB * NN];
static __device__ unsigned int g_cnt[BB];        // per-b monotonic barrier counter

__device__ __forceinline__ float wsum(float v) {
#pragma unroll
    for (int o = 16; o; o >>= 1) v += __shfl_xor_sync(0xffffffffu, v, o);
    return v;
}
__device__ __forceinline__ float hsum16(float v) {
#pragma unroll
    for (int o = 8; o; o >>= 1) v += __shfl_xor_sync(0xffffffffu, v, o);
    return v;
}
__device__ __forceinline__ float hmax16(float v) {
#pragma unroll
    for (int o = 8; o; o >>= 1) v = fmaxf(v, __shfl_xor_sync(0xffffffffu, v, o));
    return v;
}

// ---- xn[b][i] = sum_f X^2 (kept separate: must match reference summation numerics) ----
__global__ void xn_kernel(const float* __restrict__ X) {
    int b = blockIdx.x;
    int w = threadIdx.x >> 5, lane = threadIdx.x & 31;
    for (int l = w; l < NN; l += 8) {
        const float4* xr = (const float4*)(X + ((size_t)b * NN + l) * FF);
        float acc = 0.f;
#pragma unroll
        for (int q = 0; q < FF / 128; q++) {
            float4 v = xr[lane + 32 * q];
            acc += v.x * v.x + v.y * v.y + v.z * v.z + v.w * v.w;
        }
        acc = wsum(acc);
        if (lane == 0) g_xn[b * NN + l] = acc;
    }
}

// ---- G = X X^T per b, 64x64 tiles ----
__global__ void gemm_kernel(const float* __restrict__ X) {
    int b = blockIdx.z;
    int ti = blockIdx.y * 64, tj = blockIdx.x * 64;
    __shared__ float As[16][64];
    __shared__ float Bs[16][64];
    const float* Xb = X + (size_t)b * NN * FF;
    int t = threadIdx.x;
    int lr = t >> 2, lq = t & 3;
    int tx = t & 15, ty = t >> 4;
    float acc[4][4];
#pragma unroll
    for (int i = 0; i < 4; i++)
#pragma unroll
        for (int j = 0; j < 4; j++) acc[i][j] = 0.f;

    for (int kc = 0; kc < FF; kc += 16) {
        float4 av = *(const float4*)(Xb + (size_t)(ti + lr) * FF + kc + lq * 4);
        float4 bv = *(const float4*)(Xb + (size_t)(tj + lr) * FF + kc + lq * 4);
        if (kc) __syncthreads();
        As[lq * 4 + 0][lr] = av.x; As[lq * 4 + 1][lr] = av.y;
        As[lq * 4 + 2][lr] = av.z; As[lq * 4 + 3][lr] = av.w;
        Bs[lq * 4 + 0][lr] = bv.x; Bs[lq * 4 + 1][lr] = bv.y;
        Bs[lq * 4 + 2][lr] = bv.z; Bs[lq * 4 + 3][lr] = bv.w;
        __syncthreads();
#pragma unroll
        for (int kk = 0; kk < 16; kk++) {
            float4 af = *(const float4*)&As[kk][ty * 4];
            float4 bf = *(const float4*)&Bs[kk][tx * 4];
            float a[4] = {af.x, af.y, af.z, af.w};
            float bb4[4] = {bf.x, bf.y, bf.z, bf.w};
#pragma unroll
            for (int i = 0; i < 4; i++)
#pragma unroll
                for (int j = 0; j < 4; j++) acc[i][j] = fmaf(a[i], bb4[j], acc[i][j]);
        }
    }
#pragma unroll
    for (int i = 0; i < 4; i++) {
        float4 o; o.x = acc[i][0]; o.y = acc[i][1]; o.z = acc[i][2]; o.w = acc[i][3];
        *(float4*)(g_C + ((size_t)b * NN + ti + ty * 4 + i) * NN + tj + tx * 4) = o;
    }
}

// ---- C = clip(dist - diag_col, 0) in-place + row sums ----
__global__ void finC_kernel() {
    int b = blockIdx.x;
    __shared__ float xns[NN], dgv[NN];
    float* Gb = g_C + (size_t)b * NN * NN;
    for (int j = threadIdx.x; j < NN; j += 256) {
        float xj = g_xn[b * NN + j];
        xns[j] = xj;
        dgv[j] = xj + xj - 2.0f * Gb[j * NN + j];
    }
    __syncthreads();
    int w = threadIdx.x >> 5, lane = threadIdx.x & 31;
    for (int i = w; i < NN; i += 8) {
        float xi = xns[i];
        float4 g = *(float4*)(Gb + i * NN + lane * 4);
        float c0 = fmaxf(xi + xns[lane * 4 + 0] - 2.0f * g.x - dgv[lane * 4 + 0], 0.f);
        float c1 = fmaxf(xi + xns[lane * 4 + 1] - 2.0f * g.y - dgv[lane * 4 + 1], 0.f);
        float c2 = fmaxf(xi + xns[lane * 4 + 2] - 2.0f * g.z - dgv[lane * 4 + 2], 0.f);
        float c3 = fmaxf(xi + xns[lane * 4 + 3] - 2.0f * g.w - dgv[lane * 4 + 3], 0.f);
        *(float4*)(Gb + i * NN + lane * 4) = make_float4(c0, c1, c2, c3);
        float rs = wsum(c0 + c1 + c2 + c3);
        if (lane == 0) g_Crow[b * NN + i] = rs;
    }
}

// ---- init: a0 per (b,k); also reset per-b barrier counters ----
__global__ void init0_kernel(const float* __restrict__ Q, const float* __restrict__ theta) {
    int k = blockIdx.x, b = blockIdx.y;
    int tid = threadIdx.x;  // 128
    float v = Q[(b * KK + k) * NN + tid] * g_Crow[b * NN + tid] * (1.0f / NN);
    __shared__ float part[4];
    v = wsum(v);
    if ((tid & 31) == 0) part[tid >> 5] = v;
    __syncthreads();
    if (tid == 0) {
        float c = part[0] + part[1] + part[2] + part[3];
        float pen = c - theta[b * KK + k];
        g_a0[b * KK + k] = (pen > 0.f) ? (2.f * RHOc * pen) : 0.f;
        if (k == 0) g_cnt[b] = 0u;
    }
}

// ---- persistent solver: all 30 iterations, S resident in smem ----
#define SM_S    0
#define SM_W    16384
#define SM_Q    16512
#define SM_PW   16640
#define SM_CST  17664
#define SM_A    17672
#define SM_FLOATS 17676
#define SMEM_BYTES (SM_FLOATS * 4)

__global__ void __launch_bounds__(256, 3) solve_kernel(
        const float* __restrict__ Q, const float* __restrict__ theta,
        float* __restrict__ p_out) {
    extern __shared__ float sm[];
    float* S   = sm + SM_S;    // 128x128 softmax probs
    float* w_s = sm + SM_W;    // min-gradient weights
    float* q_s = sm + SM_Q;    // Q row
    float* p_w = sm + SM_PW;   // per-warp partial p [8][128]
    float* cst = sm + SM_CST;  // per-warp cost partials [8]
    float* a_s = sm + SM_A;

    int bk = blockIdx.x;
    int b = bk / KK, k = bk % KK;
    int tid = threadIdx.x;
    int warp = tid >> 5, lane = tid & 31;
    int h = lane >> 4, hl = lane & 15;
    int j0 = hl * 4, j1 = 64 + hl * 4;

    const float* Cb = g_C + (size_t)b * NN * NN;
    if (tid < NN) {
        q_s[tid] = Q[(b * KK + k) * NN + tid];
        w_s[tid] = 0.f;   // iter 0: constant w cancels in (G - <s,G>)
    }
    float th = theta[b * KK + k];
    float a = g_a0[b * KK + k];
    __syncthreads();

    for (int it = 0; it < NITER; ++it) {
        const bool first = (it == 0);
        const bool last = (it == NITER - 1);
        float pacc[8];
#pragma unroll
        for (int i = 0; i < 8; i++) pacc[i] = 0.f;
        float cacc = 0.f;

#pragma unroll
        for (int pass = 0; pass < 8; ++pass) {
            int l = pass * 16 + warp * 2 + h;
            float ql = q_s[l];
            float4 ca = __ldg((const float4*)(Cb + l * NN + j0));
            float4 cb = __ldg((const float4*)(Cb + l * NN + j1));
            float c[8] = {ca.x, ca.y, ca.z, ca.w, cb.x, cb.y, cb.z, cb.w};
            float s[8];
            if (first) {
#pragma unroll
                for (int i = 0; i < 8; i++) s[i] = 0.0078125f;
            } else {
                float4 sa = *(float4*)&S[l * NN + j0];
                float4 sb = *(float4*)&S[l * NN + j1];
                s[0] = sa.x; s[1] = sa.y; s[2] = sa.z; s[3] = sa.w;
                s[4] = sb.x; s[5] = sb.y; s[6] = sb.z; s[7] = sb.w;
            }
            float4 wa = *(float4*)&w_s[j0];
            float4 wb = *(float4*)&w_s[j1];
            float wv[8] = {wa.x, wa.y, wa.z, wa.w, wb.x, wb.y, wb.z, wb.w};

            float G[8], ms = 0.f;
#pragma unroll
            for (int i = 0; i < 8; i++) {
                G[i] = fmaf(-a, c[i], wv[i]);
                ms = fmaf(s[i], G[i], ms);
            }
            ms = hsum16(ms);

            float lq = LRc * ql;
            float d[8], M = -3.0e38f;
#pragma unroll
            for (int i = 0; i < 8; i++) {
                d[i] = (s[i] > 0.f) ? lq * s[i] * (G[i] - ms) : -3.0e38f;
                M = fmaxf(M, d[i]);
            }
            M = hmax16(M);

            float e[8], r = 0.f;
#pragma unroll
            for (int i = 0; i < 8; i++) {
                e[i] = s[i] * __expf(d[i] - M);
                r += e[i];
            }
            r = hsum16(r);
            float ir = 1.0f / r;

            float cd = 0.f;
#pragma unroll
            for (int i = 0; i < 8; i++) {
                e[i] = e[i] * ir;
                pacc[i] = fmaf(ql, e[i], pacc[i]);
                cd = fmaf(e[i], c[i], cd);
            }
            cacc = fmaf(ql, cd, cacc);

            if (!last) {
                *(float4*)&S[l * NN + j0] = make_float4(e[0], e[1], e[2], e[3]);
                *(float4*)&S[l * NN + j1] = make_float4(e[4], e[5], e[6], e[7]);
            }
        }

#pragma unroll
        for (int i = 0; i < 8; i++) pacc[i] += __shfl_xor_sync(0xffffffffu, pacc[i], 16);
        if (h == 0) {
            *(float4*)&p_w[warp * NN + j0] = make_float4(pacc[0], pacc[1], pacc[2], pacc[3]);
            *(float4*)&p_w[warp * NN + j1] = make_float4(pacc[4], pacc[5], pacc[6], pacc[7]);
        }
        cacc = wsum(cacc);
        if (lane == 0) cst[warp] = cacc;
        __syncthreads();

        float pj = 0.f;
        if (tid < NN) {
#pragma unroll
            for (int w2 = 0; w2 < 8; w2++) pj += p_w[w2 * NN + tid];
        }
        if (last) {
            if (tid < NN) p_out[(b * KK + k) * NN + tid] = pj;
            return;
        }

        int buf = it & 1;
        if (tid < NN) g_P[buf][(b * KK + k) * NN + tid] = pj;
        if (tid == 0) {
            float cc = cst[0] + cst[1] + cst[2] + cst[3] +
                       cst[4] + cst[5] + cst[6] + cst[7];
            float pen = cc - th;
            a_s[0] = (pen > 0.f) ? (2.f * RHOc * pen) : 0.f;
        }
        __syncthreads();           // all g_P stores + a_s done block-wide
        if (tid == 0) {
            __threadfence();       // release block's g_P stores to gpu scope
            atomicAdd(&g_cnt[b], 1u);
            unsigned int target = 10u * (unsigned int)(it + 1);
            while (atomicAdd(&g_cnt[b], 0u) < target) __nanosleep(128);
            __threadfence();       // acquire peers' g_P stores
        }
        __syncthreads();

        a = a_s[0];
        if (tid < NN) {
            float pv[KK];
            float mn = 3.402823466e38f;
#pragma unroll
            for (int kk = 0; kk < KK; kk++) {
                pv[kk] = g_P[buf][(b * KK + kk) * NN + tid];
                mn = fminf(mn, pv[kk]);
            }
            float cnt2 = 0.f;
#pragma unroll
            for (int kk = 0; kk < KK; kk++) cnt2 += (pv[kk] == mn) ? 1.f : 0.f;
            w_s[tid] = (pv[k] == mn) ? (1.f / cnt2) : 0.f;
        }
        __syncthreads();
    }
}

extern "C" void kernel_launch(void* const* d_in, const int* in_sizes, int n_in,
                              void* d_out, int out_size) {
    const float* X     = (const float*)d_in[0];  // [32,128,512]
    const float* Qp    = (const float*)d_in[1];  // [32,10,128]
    const float* theta = (const float*)d_in[2];  // [32,10]
    float* out = (float*)d_out;                  // [32,10,128]

    cudaFuncSetAttribute(solve_kernel,
                         cudaFuncAttributeMaxDynamicSharedMemorySize, SMEM_BYTES);

    xn_kernel<<<BB, 256>>>(X);
    gemm_kernel<<<dim3(2, 2, BB), 256>>>(X);
    finC_kernel<<<BB, 256>>>();
    init0_kernel<<<dim3(KK, BB), 128>>>(Qp, theta);
    solve_kernel<<<BB * KK, 256, SMEM_BYTES>>>(Qp, theta, out);
}